// round 4
// baseline (speedup 1.0000x reference)
#include <cuda_runtime.h>
#include <cuda_fp16.h>

#define V_    100000
#define B_    1024
#define L_    50
#define D_    128
#define KG_   50
#define TD_   384      // 3*D
#define HID_  256      // 2*D
#define MIN_  228      // D + 2*KG
#define INV2048 4.8828125e-4f

// ---------------- static device scratch ----------------
__device__ float  g_part[200 * 128];
__device__ float  g_mean[64];
__device__ float  g_invstd[64];
__device__ float  g_gx[(size_t)B_ * L_ * TD_];     // 78.6 MB
__device__ __half g_WihHi[TD_ * D_];
__device__ __half g_WihLo[TD_ * D_];
__device__ __half g_WhhH[TD_ * D_];
__device__ __half g_fcHi[(size_t)V_ * HID_];       // 51.2 MB
__device__ __half g_fcLo[(size_t)V_ * HID_];       // 51.2 MB
__device__ float  g_mlpWT[MIN_ * HID_];
__device__ float  g_head[B_ * MIN_];
__device__ float  g_hidF[B_ * HID_];

// ---------------- helpers ----------------
__device__ __forceinline__ void mma16816(float c[4], const unsigned a[4],
                                         unsigned b0, unsigned b1) {
    asm volatile(
        "mma.sync.aligned.m16n8k16.row.col.f32.f16.f16.f32 "
        "{%0,%1,%2,%3}, {%4,%5,%6,%7}, {%8,%9}, {%0,%1,%2,%3};"
        : "+f"(c[0]), "+f"(c[1]), "+f"(c[2]), "+f"(c[3])
        : "r"(a[0]), "r"(a[1]), "r"(a[2]), "r"(a[3]), "r"(b0), "r"(b1));
}

__device__ __forceinline__ void cp_async16(void* smem_dst, const void* gmem_src) {
    unsigned s = (unsigned)__cvta_generic_to_shared(smem_dst);
    asm volatile("cp.async.cg.shared.global [%0], [%1], 16;" :: "r"(s), "l"(gmem_src));
}

__device__ __forceinline__ float sigm_f(float x) {
    return __fdividef(1.f, 1.f + __expf(-x));
}

__device__ __forceinline__ void split_pair(float a, float b, __half2& hi, __half2& lo) {
    __half ha = __float2half_rn(a), hb = __float2half_rn(b);
    hi = __halves2half2(ha, hb);
    lo = __floats2half2_rn((a - __half2float(ha)) * 2048.f,
                           (b - __half2float(hb)) * 2048.f);
}

// ---------------- K0a: kg_map per-column partial sums ----------------
__global__ void k_kgstat(const float* __restrict__ kg) {
    int c  = threadIdx.x & 63;
    int rg = threadIdx.x >> 6;
    int r0 = blockIdx.x * 500;
    float s = 0.f, q = 0.f;
    if (c < KG_) {
        for (int r = r0 + rg; r < r0 + 500; r += 4) {
            float v = kg[(size_t)r * KG_ + c];
            s += v; q += v * v;
        }
    }
    __shared__ float ss[4][64], sq[4][64];
    ss[rg][c] = s; sq[rg][c] = q;
    __syncthreads();
    if (rg == 0 && c < KG_) {
        float S = ss[0][c] + ss[1][c] + ss[2][c] + ss[3][c];
        float Q = sq[0][c] + sq[1][c] + sq[2][c] + sq[3][c];
        g_part[blockIdx.x * 128 + c]      = S;
        g_part[blockIdx.x * 128 + 64 + c] = Q;
    }
}

// ---------------- K0b: finalize mean/invstd ----------------
__global__ void k_kgfin() {
    int c = threadIdx.x;
    if (c >= KG_) return;
    float S = 0.f, Q = 0.f;
    for (int i = 0; i < 200; ++i) {
        S += g_part[i * 128 + c];
        Q += g_part[i * 128 + 64 + c];
    }
    float mu  = S / (float)V_;
    float var = Q / (float)V_ - mu * mu;
    g_mean[c]   = mu;
    g_invstd[c] = rsqrtf(var + 1e-5f);
}

// ---------------- Kw: weight conversions ----------------
__global__ void k_cvt_small(const float* __restrict__ Wih,
                            const float* __restrict__ Whh,
                            const float* __restrict__ mlpW) {
    int stride = gridDim.x * blockDim.x;
    int i = blockIdx.x * blockDim.x + threadIdx.x;
    for (int j = i; j < TD_ * D_; j += stride) {
        float w = Wih[j];
        __half h = __float2half_rn(w);
        g_WihHi[j] = h;
        g_WihLo[j] = __float2half_rn((w - __half2float(h)) * 2048.f);
        g_WhhH[j]  = __float2half_rn(Whh[j]);
    }
    for (int j = i; j < HID_ * MIN_; j += stride) {
        int o = j / MIN_, k = j % MIN_;
        g_mlpWT[k * HID_ + o] = mlpW[j];
    }
}

__global__ void k_cvt_fc(const float* __restrict__ w) {
    size_t n = (size_t)V_ * HID_ / 4;
    size_t stride = (size_t)gridDim.x * blockDim.x;
    for (size_t j = (size_t)blockIdx.x * blockDim.x + threadIdx.x; j < n; j += stride) {
        float4 v = ((const float4*)w)[j];
        __half2 h01, l01, h23, l23;
        split_pair(v.x, v.y, h01, l01);
        split_pair(v.z, v.w, h23, l23);
        ((__half2*)g_fcHi)[j * 2]     = h01;
        ((__half2*)g_fcHi)[j * 2 + 1] = h23;
        ((__half2*)g_fcLo)[j * 2]     = l01;
        ((__half2*)g_fcLo)[j * 2 + 1] = l23;
    }
}

// ---------------- K1: GX = gather(item_emb) @ Wih^T + bih  (split fp16, 3-mma) ----------------
// M=51200, N=384, K=128. CTA tile 128x128, 16 warps, warp tile 32x32.
#define GX_SMEM (4 * 128 * 136 * 2)
__global__ void __launch_bounds__(512, 1) k_gx(const int* __restrict__ seq,
                                               const float* __restrict__ emb,
                                               const float* __restrict__ bih) {
    extern __shared__ __half sm1[];
    __half* Ah = sm1;                 // 128 x 136
    __half* Al = Ah + 128 * 136;
    __half* Bh = Al + 128 * 136;
    __half* Bl = Bh + 128 * 136;
    int tid = threadIdx.x;
    int m0 = blockIdx.x * 128;
    int n0 = blockIdx.y * 128;

    // gather A rows (fp32 -> hi/lo fp16)
    #pragma unroll
    for (int it = 0; it < 8; ++it) {
        int lin = tid + it * 512;        // 0..4095
        int row = lin >> 5;
        int f4  = lin & 31;
        int v = seq[m0 + row];
        float4 x = *(const float4*)(emb + (size_t)v * D_ + f4 * 4);
        __half2 h01, l01, h23, l23;
        split_pair(x.x, x.y, h01, l01);
        split_pair(x.z, x.w, h23, l23);
        *(__half2*)(Ah + row * 136 + f4 * 4)     = h01;
        *(__half2*)(Ah + row * 136 + f4 * 4 + 2) = h23;
        *(__half2*)(Al + row * 136 + f4 * 4)     = l01;
        *(__half2*)(Al + row * 136 + f4 * 4 + 2) = l23;
    }
    // load B hi/lo
    #pragma unroll
    for (int it = 0; it < 8; ++it) {
        int lin = tid + it * 512;        // 0..4095
        int sel = lin >> 11;
        int e   = lin & 2047;
        int row = e >> 4;
        int ch  = e & 15;
        const __half* src = sel ? g_WihLo : g_WihHi;
        *(uint4*)((sel ? Bl : Bh) + row * 136 + ch * 8) =
            *(const uint4*)(src + (n0 + row) * D_ + ch * 8);
    }
    __syncthreads();

    int w = tid >> 5, lane = tid & 31;
    int wm = (w >> 2) * 32, wn = (w & 3) * 32;
    int r = lane >> 2, q = (lane & 3) * 2;

    float c1[2][4][4], c2[2][4][4];
    #pragma unroll
    for (int i = 0; i < 2; ++i)
        #pragma unroll
        for (int j = 0; j < 4; ++j)
            #pragma unroll
            for (int t = 0; t < 4; ++t) { c1[i][j][t] = 0.f; c2[i][j][t] = 0.f; }

    #pragma unroll
    for (int ks = 0; ks < 8; ++ks) {
        int k0 = ks * 16;
        unsigned ah[2][4], al[2][4];
        #pragma unroll
        for (int i = 0; i < 2; ++i) {
            const __half* bh_ = Ah + (wm + i * 16) * 136 + k0;
            const __half* bl_ = Al + (wm + i * 16) * 136 + k0;
            ah[i][0] = *(const unsigned*)(bh_ + r * 136 + q);
            ah[i][1] = *(const unsigned*)(bh_ + (r + 8) * 136 + q);
            ah[i][2] = *(const unsigned*)(bh_ + r * 136 + 8 + q);
            ah[i][3] = *(const unsigned*)(bh_ + (r + 8) * 136 + 8 + q);
            al[i][0] = *(const unsigned*)(bl_ + r * 136 + q);
            al[i][1] = *(const unsigned*)(bl_ + (r + 8) * 136 + q);
            al[i][2] = *(const unsigned*)(bl_ + r * 136 + 8 + q);
            al[i][3] = *(const unsigned*)(bl_ + (r + 8) * 136 + 8 + q);
        }
        #pragma unroll
        for (int j = 0; j < 4; ++j) {
            const __half* pbh = Bh + (wn + j * 8 + r) * 136 + k0;
            const __half* pbl = Bl + (wn + j * 8 + r) * 136 + k0;
            unsigned bh0 = *(const unsigned*)(pbh + q);
            unsigned bh1 = *(const unsigned*)(pbh + 8 + q);
            unsigned bl0 = *(const unsigned*)(pbl + q);
            unsigned bl1 = *(const unsigned*)(pbl + 8 + q);
            #pragma unroll
            for (int i = 0; i < 2; ++i) {
                mma16816(c1[i][j], ah[i], bh0, bh1);
                mma16816(c2[i][j], ah[i], bl0, bl1);
                mma16816(c2[i][j], al[i], bh0, bh1);
            }
        }
    }
    #pragma unroll
    for (int i = 0; i < 2; ++i) {
        int row = m0 + wm + i * 16 + r;
        #pragma unroll
        for (int j = 0; j < 4; ++j) {
            int col = n0 + wn + j * 8 + q;
            float b0 = __ldg(bih + col), b1 = __ldg(bih + col + 1);
            *(float2*)(g_gx + (size_t)row * TD_ + col) =
                make_float2(c1[i][j][0] + c2[i][j][0] * INV2048 + b0,
                            c1[i][j][1] + c2[i][j][1] * INV2048 + b1);
            *(float2*)(g_gx + (size_t)(row + 8) * TD_ + col) =
                make_float2(c1[i][j][2] + c2[i][j][2] * INV2048 + b0,
                            c1[i][j][3] + c2[i][j][3] * INV2048 + b1);
        }
    }
}

// ---------------- K3: batch_kg + mlph -> g_head[:,128:228] ----------------
__global__ void k_bkg(const int* __restrict__ seq, const int* __restrict__ tlen,
                      const float* __restrict__ kg,
                      const float* __restrict__ mlphW, const float* __restrict__ mlphb) {
    int b = blockIdx.x, c = threadIdx.x;
    __shared__ int   sseq[L_];
    __shared__ float sbkg[KG_];
    if (c < L_) sseq[c] = seq[b * L_ + c];
    __syncthreads();
    if (c < KG_) {
        float acc = 0.f;
        #pragma unroll 10
        for (int t = 0; t < L_; ++t) acc += kg[(size_t)sseq[t] * KG_ + c];
        float val = (acc - (float)L_ * g_mean[c]) * g_invstd[c] / (float)tlen[b];
        sbkg[c] = val;
        g_head[b * MIN_ + D_ + c] = val;
    }
    __syncthreads();
    if (c < KG_) {
        float acc = mlphb[c];
        #pragma unroll 10
        for (int k = 0; k < KG_; ++k) acc += sbkg[k] * mlphW[c * KG_ + k];
        g_head[b * MIN_ + D_ + KG_ + c] = acc;
    }
}

// ---------------- K2: GRU recurrence (8 batch rows per CTA) ----------------
#define GRU_SMEM 167968
__global__ void __launch_bounds__(256, 1) k_gru(const int* __restrict__ tlen,
                                                const float* __restrict__ bhh) {
    extern __shared__ char smraw[];
    float*  sGx  = (float*)smraw;                  // 2 x 3072
    float*  sGh  = sGx + 6144;                     // 16 x 388
    float*  sHf  = sGh + 6208;                     // 16 x 128
    float*  sBhh = sHf + 2048;                     // 384
    __half* sWhh = (__half*)(sBhh + 384);          // 384 x 136
    __half* sH16 = sWhh + 52224;                   // 16 x 136
    int*    slen = (int*)(sH16 + 2176);            // 8

    int tid = threadIdx.x;
    int rbase = blockIdx.x * 8;

    #pragma unroll
    for (int j = 0; j < 24; ++j) {
        int lin = tid + j * 256;
        int row = lin >> 4;
        int ch  = lin & 15;
        *(uint4*)(sWhh + row * 136 + ch * 8) = *(const uint4*)(g_WhhH + row * D_ + ch * 8);
    }
    for (int j = tid; j < 2048; j += 256) sHf[j] = 0.f;
    // FIX (round 3 bug): blockDim is 256; sBhh has 384 entries. The old
    // `if (tid < 384)` guard left sBhh[256..383] (the n-gate bhh) uninitialized.
    for (int j = tid; j < 384; j += 256) sBhh[j] = bhh[j];
    if (tid < 8)   slen[tid] = tlen[rbase + tid];

    #pragma unroll
    for (int j = 0; j < 3; ++j) {
        int e = tid + j * 256;
        int rr = e / 96, qq = e % 96;
        cp_async16(sGx + rr * 384 + qq * 4,
                   g_gx + ((size_t)(rbase + rr) * L_) * TD_ + qq * 4);
    }
    asm volatile("cp.async.commit_group;");
    __syncthreads();

    int maxlen = 0;
    #pragma unroll
    for (int i = 0; i < 8; ++i) maxlen = max(maxlen, slen[i]);

    int lane = tid & 31, w = tid >> 5;
    int r = lane >> 2, q2 = (lane & 3) * 2;

    for (int t = 0; t < maxlen; ++t) {
        int buf = t & 1;
        if (t + 1 < maxlen) {
            #pragma unroll
            for (int j = 0; j < 3; ++j) {
                int e = tid + j * 256;
                int rr = e / 96, qq = e % 96;
                cp_async16(sGx + (buf ^ 1) * 3072 + rr * 384 + qq * 4,
                           g_gx + ((size_t)(rbase + rr) * L_ + (t + 1)) * TD_ + qq * 4);
            }
        }
        asm volatile("cp.async.commit_group;");

        #pragma unroll
        for (int j = 0; j < 4; ++j) {
            int e = tid + j * 256;
            int rr = e >> 6, dd = (e & 63) * 2;
            *(__half2*)(sH16 + rr * 136 + dd) =
                __floats2half2_rn(sHf[rr * 128 + dd], sHf[rr * 128 + dd + 1]);
        }
        asm volatile("cp.async.wait_group 1;");
        __syncthreads();

        {
            float c[6][4];
            #pragma unroll
            for (int j = 0; j < 6; ++j) c[j][0] = c[j][1] = c[j][2] = c[j][3] = 0.f;
            #pragma unroll
            for (int ks = 0; ks < 8; ++ks) {
                int k0 = ks * 16;
                unsigned a[4];
                a[0] = *(const unsigned*)(sH16 + r * 136 + k0 + q2);
                a[1] = *(const unsigned*)(sH16 + (r + 8) * 136 + k0 + q2);
                a[2] = *(const unsigned*)(sH16 + r * 136 + k0 + 8 + q2);
                a[3] = *(const unsigned*)(sH16 + (r + 8) * 136 + k0 + 8 + q2);
                #pragma unroll
                for (int j = 0; j < 6; ++j) {
                    const __half* bb = sWhh + (w * 48 + j * 8 + r) * 136 + k0;
                    unsigned b0 = *(const unsigned*)(bb + q2);
                    unsigned b1 = *(const unsigned*)(bb + 8 + q2);
                    mma16816(c[j], a, b0, b1);
                }
            }
            #pragma unroll
            for (int j = 0; j < 6; ++j) {
                int col = w * 48 + j * 8 + q2;
                *(float2*)(sGh + r * 388 + col)       = make_float2(c[j][0], c[j][1]);
                *(float2*)(sGh + (r + 8) * 388 + col) = make_float2(c[j][2], c[j][3]);
            }
        }
        __syncthreads();

        #pragma unroll
        for (int j = 0; j < 4; ++j) {
            int e = tid + j * 256;
            int rr = e >> 7, dd = e & 127;
            if (t < slen[rr]) {
                const float* gx = sGx + buf * 3072 + rr * 384;
                float ghr = sGh[rr * 388 + dd]       + sBhh[dd];
                float ghz = sGh[rr * 388 + 128 + dd] + sBhh[128 + dd];
                float ghn = sGh[rr * 388 + 256 + dd] + sBhh[256 + dd];
                float rg = sigm_f(gx[dd] + ghr);
                float z  = sigm_f(gx[128 + dd] + ghz);
                float nn = 2.f * sigm_f(2.f * (gx[256 + dd] + rg * ghn)) - 1.f;
                float h  = sHf[rr * 128 + dd];
                sHf[rr * 128 + dd] = (1.f - z) * nn + z * h;
            }
        }
        __syncthreads();
    }
    asm volatile("cp.async.wait_all;");

    #pragma unroll
    for (int j = 0; j < 4; ++j) {
        int e = tid + j * 256;
        int rr = e >> 7, dd = e & 127;
        g_head[(rbase + rr) * MIN_ + dd] = sHf[rr * 128 + dd];
    }
}

// ---------------- K4: hidden = tanh(g_head @ mlp_W^T + mlp_b) -> fp32 ----------------
__global__ void __launch_bounds__(256) k_mlp(const float* __restrict__ mlpb) {
    __shared__ float sIn[16 * MIN_];
    int tid = threadIdx.x;
    int rbase = blockIdx.x * 16;
    for (int j = tid; j < 16 * MIN_; j += 256) {
        int rr = j / MIN_, kk = j % MIN_;
        sIn[j] = g_head[(rbase + rr) * MIN_ + kk];
    }
    __syncthreads();
    int o = tid;
    float acc[16];
    float bb = mlpb[o];
    #pragma unroll
    for (int i = 0; i < 16; ++i) acc[i] = bb;
    for (int k = 0; k < MIN_; ++k) {
        float wv = g_mlpWT[k * HID_ + o];
        #pragma unroll
        for (int i = 0; i < 16; ++i) acc[i] += sIn[i * MIN_ + k] * wv;
    }
    #pragma unroll
    for (int i = 0; i < 16; ++i)
        g_hidF[(size_t)(rbase + i) * HID_ + o] = tanhf(acc[i]);
}

// ---------------- K5: out = hidden @ fc_W^T + fc_b  (split fp16, 3-mma) ----------------
#define NTILES 782
#define FC_SMEM (128 * 264 * 2 * 2 + 128 * 136 * 2 * 2)   // 204800
__global__ void __launch_bounds__(512, 1) k_fc(const float* __restrict__ fcb,
                                               float* __restrict__ out) {
    extern __shared__ __half sm5[];
    __half* Ah = sm5;                   // 128 x 264
    __half* Al = Ah + 128 * 264;
    __half* Bh = Al + 128 * 264;        // 128 x 136
    __half* Bl = Bh + 128 * 136;
    int tid = threadIdx.x;
    int m0 = blockIdx.y * 128;

    // load + split A (hidden fp32)
    #pragma unroll
    for (int it = 0; it < 16; ++it) {
        int lin = tid + it * 512;        // 0..8191 float4
        int row = lin >> 6;
        int c4  = lin & 63;
        float4 v = *(const float4*)(g_hidF + (size_t)(m0 + row) * HID_ + c4 * 4);
        __half2 h01, l01, h23, l23;
        split_pair(v.x, v.y, h01, l01);
        split_pair(v.z, v.w, h23, l23);
        *(__half2*)(Ah + row * 264 + c4 * 4)     = h01;
        *(__half2*)(Ah + row * 264 + c4 * 4 + 2) = h23;
        *(__half2*)(Al + row * 264 + c4 * 4)     = l01;
        *(__half2*)(Al + row * 264 + c4 * 4 + 2) = l23;
    }

    int w = tid >> 5, lane = tid & 31;
    int wm = (w >> 2) * 32, wn = (w & 3) * 32;
    int r = lane >> 2, q = (lane & 3) * 2;

    for (int nt = blockIdx.x; nt < NTILES; nt += gridDim.x) {
        int n0 = nt * 128;
        float c1[2][4][4], c2[2][4][4];
        #pragma unroll
        for (int i = 0; i < 2; ++i)
            #pragma unroll
            for (int j = 0; j < 4; ++j)
                #pragma unroll
                for (int t = 0; t < 4; ++t) { c1[i][j][t] = 0.f; c2[i][j][t] = 0.f; }

        #pragma unroll
        for (int kc = 0; kc < 2; ++kc) {
            __syncthreads();
            #pragma unroll
            for (int it = 0; it < 8; ++it) {
                int lin = tid + it * 512;    // 0..4095
                int sel = lin >> 11;
                int e   = lin & 2047;
                int row = e >> 4;
                int ch  = e & 15;
                const __half* src = sel ? g_fcLo : g_fcHi;
                uint4 v = make_uint4(0u, 0u, 0u, 0u);
                if (n0 + row < V_)
                    v = *(const uint4*)(src + (size_t)(n0 + row) * HID_ + kc * 128 + ch * 8);
                *(uint4*)((sel ? Bl : Bh) + row * 136 + ch * 8) = v;
            }
            __syncthreads();

            #pragma unroll
            for (int ks = 0; ks < 8; ++ks) {
                int k0 = ks * 16;
                int ka = kc * 128 + k0;
                unsigned ah[2][4], al[2][4];
                #pragma unroll
                for (int i = 0; i < 2; ++i) {
                    const __half* ph = Ah + (wm + i * 16) * 264 + ka;
                    const __half* pl = Al + (wm + i * 16) * 264 + ka;
                    ah[i][0] = *(const unsigned*)(ph + r * 264 + q);
                    ah[i][1] = *(const unsigned*)(ph + (r + 8) * 264 + q);
                    ah[i][2] = *(const unsigned*)(ph + r * 264 + 8 + q);
                    ah[i][3] = *(const unsigned*)(ph + (r + 8) * 264 + 8 + q);
                    al[i][0] = *(const unsigned*)(pl + r * 264 + q);
                    al[i][1] = *(const unsigned*)(pl + (r + 8) * 264 + q);
                    al[i][2] = *(const unsigned*)(pl + r * 264 + 8 + q);
                    al[i][3] = *(const unsigned*)(pl + (r + 8) * 264 + 8 + q);
                }
                #pragma unroll
                for (int j = 0; j < 4; ++j) {
                    const __half* pbh = Bh + (wn + j * 8 + r) * 136 + k0;
                    const __half* pbl = Bl + (wn + j * 8 + r) * 136 + k0;
                    unsigned bh0 = *(const unsigned*)(pbh + q);
                    unsigned bh1 = *(const unsigned*)(pbh + 8 + q);
                    unsigned bl0 = *(const unsigned*)(pbl + q);
                    unsigned bl1 = *(const unsigned*)(pbl + 8 + q);
                    #pragma unroll
                    for (int i = 0; i < 2; ++i) {
                        mma16816(c1[i][j], ah[i], bh0, bh1);
                        mma16816(c2[i][j], ah[i], bl0, bl1);
                        mma16816(c2[i][j], al[i], bh0, bh1);
                    }
                }
            }
        }

        #pragma unroll
        for (int i = 0; i < 2; ++i) {
            int row = m0 + wm + i * 16 + r;
            #pragma unroll
            for (int j = 0; j < 4; ++j) {
                int col = n0 + wn + j * 8 + q;
                if (col < V_) {
                    float b0 = __ldg(fcb + col), b1 = __ldg(fcb + col + 1);
                    *(float2*)(out + (size_t)row * V_ + col) =
                        make_float2(c1[i][j][0] + c2[i][j][0] * INV2048 + b0,
                                    c1[i][j][1] + c2[i][j][1] * INV2048 + b1);
                    *(float2*)(out + (size_t)(row + 8) * V_ + col) =
                        make_float2(c1[i][j][2] + c2[i][j][2] * INV2048 + b0,
                                    c1[i][j][3] + c2[i][j][3] * INV2048 + b1);
                }
            }
        }
    }
}

// ---------------- launch ----------------
extern "C" void kernel_launch(void* const* d_in, const int* in_sizes, int n_in,
                              void* d_out, int out_size) {
    const int*   seq   = (const int*)d_in[0];
    const int*   tlen  = (const int*)d_in[1];
    const float* emb   = (const float*)d_in[2];
    const float* kg    = (const float*)d_in[3];
    const float* Wih   = (const float*)d_in[4];
    const float* Whh   = (const float*)d_in[5];
    const float* bih   = (const float*)d_in[6];
    const float* bhh   = (const float*)d_in[7];
    const float* mlphW = (const float*)d_in[8];
    const float* mlphb = (const float*)d_in[9];
    const float* mlpW  = (const float*)d_in[10];
    const float* mlpb  = (const float*)d_in[11];
    const float* fcW   = (const float*)d_in[12];
    const float* fcb   = (const float*)d_in[13];
    float* out = (float*)d_out;

    cudaFuncSetAttribute(k_gx,  cudaFuncAttributeMaxDynamicSharedMemorySize, GX_SMEM);
    cudaFuncSetAttribute(k_gru, cudaFuncAttributeMaxDynamicSharedMemorySize, GRU_SMEM);
    cudaFuncSetAttribute(k_fc,  cudaFuncAttributeMaxDynamicSharedMemorySize, FC_SMEM);

    k_kgstat<<<200, 256>>>(kg);
    k_kgfin<<<1, 64>>>();
    k_cvt_small<<<192, 256>>>(Wih, Whh, mlpW);
    k_cvt_fc<<<2048, 256>>>(fcW);
    k_gx<<<dim3(400, 3), 512, GX_SMEM>>>(seq, emb, bih);
    k_bkg<<<1024, 64>>>(seq, tlen, kg, mlphW, mlphb);
    k_gru<<<128, 256, GRU_SMEM>>>(tlen, bhh);
    k_mlp<<<64, 256>>>(mlpb);
    k_fc<<<dim3(37, 8), 512, FC_SMEM>>>(fcb, out);
}

// round 7
// speedup vs baseline: 1.6618x; 1.6618x over previous
#include <cuda_runtime.h>
#include <cuda_fp16.h>

#define V_    100000
#define B_    1024
#define L_    50
#define D_    128
#define KG_   50
#define TD_   384      // 3*D
#define HID_  256      // 2*D
#define MIN_  228      // D + 2*KG
#define INV2048 4.8828125e-4f

// ---------------- static device scratch ----------------
__device__ float  g_part[200 * 128];
__device__ float  g_mean[64];
__device__ float  g_invstd[64];
__device__ float  g_gx[(size_t)B_ * L_ * TD_];     // 78.6 MB
__device__ __half g_WihHi[TD_ * D_];
__device__ __half g_WihLo[TD_ * D_];
__device__ __half g_WhhH[TD_ * D_];
__device__ __half g_fcHi[(size_t)V_ * HID_];       // 51.2 MB (fits in L2)
__device__ float  g_mlpWT[MIN_ * HID_];
__device__ float  g_head[B_ * MIN_];
__device__ float  g_hidF[B_ * HID_];

// ---------------- helpers ----------------
__device__ __forceinline__ void mma16816(float c[4], const unsigned a[4],
                                         unsigned b0, unsigned b1) {
    asm volatile(
        "mma.sync.aligned.m16n8k16.row.col.f32.f16.f16.f32 "
        "{%0,%1,%2,%3}, {%4,%5,%6,%7}, {%8,%9}, {%0,%1,%2,%3};"
        : "+f"(c[0]), "+f"(c[1]), "+f"(c[2]), "+f"(c[3])
        : "r"(a[0]), "r"(a[1]), "r"(a[2]), "r"(a[3]), "r"(b0), "r"(b1));
}

__device__ __forceinline__ void cp_async16(void* smem_dst, const void* gmem_src) {
    unsigned s = (unsigned)__cvta_generic_to_shared(smem_dst);
    asm volatile("cp.async.cg.shared.global [%0], [%1], 16;" :: "r"(s), "l"(gmem_src));
}

__device__ __forceinline__ float sigm_f(float x) {
    return __fdividef(1.f, 1.f + __expf(-x));
}

__device__ __forceinline__ void split_pair(float a, float b, __half2& hi, __half2& lo) {
    __half ha = __float2half_rn(a), hb = __float2half_rn(b);
    hi = __halves2half2(ha, hb);
    lo = __floats2half2_rn((a - __half2float(ha)) * 2048.f,
                           (b - __half2float(hb)) * 2048.f);
}

// ---------------- K0a: kg_map per-column partial sums ----------------
__global__ void k_kgstat(const float* __restrict__ kg) {
    int c  = threadIdx.x & 63;
    int rg = threadIdx.x >> 6;
    int r0 = blockIdx.x * 500;
    float s = 0.f, q = 0.f;
    if (c < KG_) {
        for (int r = r0 + rg; r < r0 + 500; r += 4) {
            float v = kg[(size_t)r * KG_ + c];
            s += v; q += v * v;
        }
    }
    __shared__ float ss[4][64], sq[4][64];
    ss[rg][c] = s; sq[rg][c] = q;
    __syncthreads();
    if (rg == 0 && c < KG_) {
        float S = ss[0][c] + ss[1][c] + ss[2][c] + ss[3][c];
        float Q = sq[0][c] + sq[1][c] + sq[2][c] + sq[3][c];
        g_part[blockIdx.x * 128 + c]      = S;
        g_part[blockIdx.x * 128 + 64 + c] = Q;
    }
}

// ---------------- K0b: finalize mean/invstd ----------------
__global__ void k_kgfin() {
    int c = threadIdx.x;
    if (c >= KG_) return;
    float S = 0.f, Q = 0.f;
    for (int i = 0; i < 200; ++i) {
        S += g_part[i * 128 + c];
        Q += g_part[i * 128 + 64 + c];
    }
    float mu  = S / (float)V_;
    float var = Q / (float)V_ - mu * mu;
    g_mean[c]   = mu;
    g_invstd[c] = rsqrtf(var + 1e-5f);
}

// ---------------- Kw: weight conversions ----------------
__global__ void k_cvt_small(const float* __restrict__ Wih,
                            const float* __restrict__ Whh,
                            const float* __restrict__ mlpW) {
    int stride = gridDim.x * blockDim.x;
    int i = blockIdx.x * blockDim.x + threadIdx.x;
    for (int j = i; j < TD_ * D_; j += stride) {
        float w = Wih[j];
        __half h = __float2half_rn(w);
        g_WihHi[j] = h;
        g_WihLo[j] = __float2half_rn((w - __half2float(h)) * 2048.f);
        g_WhhH[j]  = __float2half_rn(Whh[j]);
    }
    for (int j = i; j < HID_ * MIN_; j += stride) {
        int o = j / MIN_, k = j % MIN_;
        g_mlpWT[k * HID_ + o] = mlpW[j];
    }
}

__global__ void k_cvt_fc(const float* __restrict__ w) {
    size_t n = (size_t)V_ * HID_ / 4;
    size_t stride = (size_t)gridDim.x * blockDim.x;
    for (size_t j = (size_t)blockIdx.x * blockDim.x + threadIdx.x; j < n; j += stride) {
        float4 v = ((const float4*)w)[j];
        ((__half2*)g_fcHi)[j * 2]     = __floats2half2_rn(v.x, v.y);
        ((__half2*)g_fcHi)[j * 2 + 1] = __floats2half2_rn(v.z, v.w);
    }
}

// ---------------- K1: GX = gather(item_emb) @ Wih^T + bih  (split fp16, 3-mma) ----------------
#define GX_SMEM (4 * 128 * 136 * 2)
__global__ void __launch_bounds__(512, 1) k_gx(const int* __restrict__ seq,
                                               const float* __restrict__ emb,
                                               const float* __restrict__ bih) {
    extern __shared__ __half sm1[];
    __half* Ah = sm1;                 // 128 x 136
    __half* Al = Ah + 128 * 136;
    __half* Bh = Al + 128 * 136;
    __half* Bl = Bh + 128 * 136;
    int tid = threadIdx.x;
    int m0 = blockIdx.x * 128;
    int n0 = blockIdx.y * 128;

    #pragma unroll
    for (int it = 0; it < 8; ++it) {
        int lin = tid + it * 512;        // 0..4095
        int row = lin >> 5;
        int f4  = lin & 31;
        int v = seq[m0 + row];
        float4 x = *(const float4*)(emb + (size_t)v * D_ + f4 * 4);
        __half2 h01, l01, h23, l23;
        split_pair(x.x, x.y, h01, l01);
        split_pair(x.z, x.w, h23, l23);
        *(__half2*)(Ah + row * 136 + f4 * 4)     = h01;
        *(__half2*)(Ah + row * 136 + f4 * 4 + 2) = h23;
        *(__half2*)(Al + row * 136 + f4 * 4)     = l01;
        *(__half2*)(Al + row * 136 + f4 * 4 + 2) = l23;
    }
    #pragma unroll
    for (int it = 0; it < 8; ++it) {
        int lin = tid + it * 512;        // 0..4095
        int sel = lin >> 11;
        int e   = lin & 2047;
        int row = e >> 4;
        int ch  = e & 15;
        const __half* src = sel ? g_WihLo : g_WihHi;
        *(uint4*)((sel ? Bl : Bh) + row * 136 + ch * 8) =
            *(const uint4*)(src + (n0 + row) * D_ + ch * 8);
    }
    __syncthreads();

    int w = tid >> 5, lane = tid & 31;
    int wm = (w >> 2) * 32, wn = (w & 3) * 32;
    int r = lane >> 2, q = (lane & 3) * 2;

    float c1[2][4][4], c2[2][4][4];
    #pragma unroll
    for (int i = 0; i < 2; ++i)
        #pragma unroll
        for (int j = 0; j < 4; ++j)
            #pragma unroll
            for (int t = 0; t < 4; ++t) { c1[i][j][t] = 0.f; c2[i][j][t] = 0.f; }

    #pragma unroll
    for (int ks = 0; ks < 8; ++ks) {
        int k0 = ks * 16;
        unsigned ah[2][4], al[2][4];
        #pragma unroll
        for (int i = 0; i < 2; ++i) {
            const __half* bh_ = Ah + (wm + i * 16) * 136 + k0;
            const __half* bl_ = Al + (wm + i * 16) * 136 + k0;
            ah[i][0] = *(const unsigned*)(bh_ + r * 136 + q);
            ah[i][1] = *(const unsigned*)(bh_ + (r + 8) * 136 + q);
            ah[i][2] = *(const unsigned*)(bh_ + r * 136 + 8 + q);
            ah[i][3] = *(const unsigned*)(bh_ + (r + 8) * 136 + 8 + q);
            al[i][0] = *(const unsigned*)(bl_ + r * 136 + q);
            al[i][1] = *(const unsigned*)(bl_ + (r + 8) * 136 + q);
            al[i][2] = *(const unsigned*)(bl_ + r * 136 + 8 + q);
            al[i][3] = *(const unsigned*)(bl_ + (r + 8) * 136 + 8 + q);
        }
        #pragma unroll
        for (int j = 0; j < 4; ++j) {
            const __half* pbh = Bh + (wn + j * 8 + r) * 136 + k0;
            const __half* pbl = Bl + (wn + j * 8 + r) * 136 + k0;
            unsigned bh0 = *(const unsigned*)(pbh + q);
            unsigned bh1 = *(const unsigned*)(pbh + 8 + q);
            unsigned bl0 = *(const unsigned*)(pbl + q);
            unsigned bl1 = *(const unsigned*)(pbl + 8 + q);
            #pragma unroll
            for (int i = 0; i < 2; ++i) {
                mma16816(c1[i][j], ah[i], bh0, bh1);
                mma16816(c2[i][j], ah[i], bl0, bl1);
                mma16816(c2[i][j], al[i], bh0, bh1);
            }
        }
    }
    #pragma unroll
    for (int i = 0; i < 2; ++i) {
        int row = m0 + wm + i * 16 + r;
        #pragma unroll
        for (int j = 0; j < 4; ++j) {
            int col = n0 + wn + j * 8 + q;
            float b0 = __ldg(bih + col), b1 = __ldg(bih + col + 1);
            *(float2*)(g_gx + (size_t)row * TD_ + col) =
                make_float2(c1[i][j][0] + c2[i][j][0] * INV2048 + b0,
                            c1[i][j][1] + c2[i][j][1] * INV2048 + b1);
            *(float2*)(g_gx + (size_t)(row + 8) * TD_ + col) =
                make_float2(c1[i][j][2] + c2[i][j][2] * INV2048 + b0,
                            c1[i][j][3] + c2[i][j][3] * INV2048 + b1);
        }
    }
}

// ---------------- K3: batch_kg + mlph -> g_head[:,128:228] ----------------
__global__ void k_bkg(const int* __restrict__ seq, const int* __restrict__ tlen,
                      const float* __restrict__ kg,
                      const float* __restrict__ mlphW, const float* __restrict__ mlphb) {
    int b = blockIdx.x, c = threadIdx.x;
    __shared__ int   sseq[L_];
    __shared__ float sbkg[KG_];
    if (c < L_) sseq[c] = seq[b * L_ + c];
    __syncthreads();
    if (c < KG_) {
        float acc = 0.f;
        #pragma unroll 10
        for (int t = 0; t < L_; ++t) acc += kg[(size_t)sseq[t] * KG_ + c];
        float val = (acc - (float)L_ * g_mean[c]) * g_invstd[c] / (float)tlen[b];
        sbkg[c] = val;
        g_head[b * MIN_ + D_ + c] = val;
    }
    __syncthreads();
    if (c < KG_) {
        float acc = mlphb[c];
        #pragma unroll 10
        for (int k = 0; k < KG_; ++k) acc += sbkg[k] * mlphW[c * KG_ + k];
        g_head[b * MIN_ + D_ + KG_ + c] = acc;
    }
}

// ---------------- K2: GRU recurrence (8 batch rows per CTA) ----------------
#define GRU_SMEM 167968
__global__ void __launch_bounds__(256, 1) k_gru(const int* __restrict__ tlen,
                                                const float* __restrict__ bhh) {
    extern __shared__ char smraw[];
    float*  sGx  = (float*)smraw;                  // 2 x 3072
    float*  sGh  = sGx + 6144;                     // 16 x 388
    float*  sHf  = sGh + 6208;                     // 16 x 128
    float*  sBhh = sHf + 2048;                     // 384
    __half* sWhh = (__half*)(sBhh + 384);          // 384 x 136
    __half* sH16 = sWhh + 52224;                   // 16 x 136
    int*    slen = (int*)(sH16 + 2176);            // 8

    int tid = threadIdx.x;
    int rbase = blockIdx.x * 8;

    #pragma unroll
    for (int j = 0; j < 24; ++j) {
        int lin = tid + j * 256;
        int row = lin >> 4;
        int ch  = lin & 15;
        *(uint4*)(sWhh + row * 136 + ch * 8) = *(const uint4*)(g_WhhH + row * D_ + ch * 8);
    }
    for (int j = tid; j < 2048; j += 256) sHf[j] = 0.f;
    for (int j = tid; j < 384; j += 256) sBhh[j] = bhh[j];
    if (tid < 8)   slen[tid] = tlen[rbase + tid];

    #pragma unroll
    for (int j = 0; j < 3; ++j) {
        int e = tid + j * 256;
        int rr = e / 96, qq = e % 96;
        cp_async16(sGx + rr * 384 + qq * 4,
                   g_gx + ((size_t)(rbase + rr) * L_) * TD_ + qq * 4);
    }
    asm volatile("cp.async.commit_group;");
    __syncthreads();

    int maxlen = 0;
    #pragma unroll
    for (int i = 0; i < 8; ++i) maxlen = max(maxlen, slen[i]);

    int lane = tid & 31, w = tid >> 5;
    int r = lane >> 2, q2 = (lane & 3) * 2;

    for (int t = 0; t < maxlen; ++t) {
        int buf = t & 1;
        if (t + 1 < maxlen) {
            #pragma unroll
            for (int j = 0; j < 3; ++j) {
                int e = tid + j * 256;
                int rr = e / 96, qq = e % 96;
                cp_async16(sGx + (buf ^ 1) * 3072 + rr * 384 + qq * 4,
                           g_gx + ((size_t)(rbase + rr) * L_ + (t + 1)) * TD_ + qq * 4);
            }
        }
        asm volatile("cp.async.commit_group;");

        #pragma unroll
        for (int j = 0; j < 4; ++j) {
            int e = tid + j * 256;
            int rr = e >> 6, dd = (e & 63) * 2;
            *(__half2*)(sH16 + rr * 136 + dd) =
                __floats2half2_rn(sHf[rr * 128 + dd], sHf[rr * 128 + dd + 1]);
        }
        asm volatile("cp.async.wait_group 1;");
        __syncthreads();

        {
            float c[6][4];
            #pragma unroll
            for (int j = 0; j < 6; ++j) c[j][0] = c[j][1] = c[j][2] = c[j][3] = 0.f;
            #pragma unroll
            for (int ks = 0; ks < 8; ++ks) {
                int k0 = ks * 16;
                unsigned a[4];
                a[0] = *(const unsigned*)(sH16 + r * 136 + k0 + q2);
                a[1] = *(const unsigned*)(sH16 + (r + 8) * 136 + k0 + q2);
                a[2] = *(const unsigned*)(sH16 + r * 136 + k0 + 8 + q2);
                a[3] = *(const unsigned*)(sH16 + (r + 8) * 136 + k0 + 8 + q2);
                #pragma unroll
                for (int j = 0; j < 6; ++j) {
                    const __half* bb = sWhh + (w * 48 + j * 8 + r) * 136 + k0;
                    unsigned b0 = *(const unsigned*)(bb + q2);
                    unsigned b1 = *(const unsigned*)(bb + 8 + q2);
                    mma16816(c[j], a, b0, b1);
                }
            }
            #pragma unroll
            for (int j = 0; j < 6; ++j) {
                int col = w * 48 + j * 8 + q2;
                *(float2*)(sGh + r * 388 + col)       = make_float2(c[j][0], c[j][1]);
                *(float2*)(sGh + (r + 8) * 388 + col) = make_float2(c[j][2], c[j][3]);
            }
        }
        __syncthreads();

        #pragma unroll
        for (int j = 0; j < 4; ++j) {
            int e = tid + j * 256;
            int rr = e >> 7, dd = e & 127;
            if (t < slen[rr]) {
                const float* gx = sGx + buf * 3072 + rr * 384;
                float ghr = sGh[rr * 388 + dd]       + sBhh[dd];
                float ghz = sGh[rr * 388 + 128 + dd] + sBhh[128 + dd];
                float ghn = sGh[rr * 388 + 256 + dd] + sBhh[256 + dd];
                float rg = sigm_f(gx[dd] + ghr);
                float z  = sigm_f(gx[128 + dd] + ghz);
                float nn = 2.f * sigm_f(2.f * (gx[256 + dd] + rg * ghn)) - 1.f;
                float h  = sHf[rr * 128 + dd];
                sHf[rr * 128 + dd] = (1.f - z) * nn + z * h;
            }
        }
        __syncthreads();
    }
    asm volatile("cp.async.wait_all;");

    #pragma unroll
    for (int j = 0; j < 4; ++j) {
        int e = tid + j * 256;
        int rr = e >> 7, dd = e & 127;
        g_head[(rbase + rr) * MIN_ + dd] = sHf[rr * 128 + dd];
    }
}

// ---------------- K4: hidden = tanh(g_head @ mlp_W^T + mlp_b) -> fp32 ----------------
__global__ void __launch_bounds__(256) k_mlp(const float* __restrict__ mlpb) {
    __shared__ float sIn[16 * MIN_];
    int tid = threadIdx.x;
    int rbase = blockIdx.x * 16;
    for (int j = tid; j < 16 * MIN_; j += 256) {
        int rr = j / MIN_, kk = j % MIN_;
        sIn[j] = g_head[(rbase + rr) * MIN_ + kk];
    }
    __syncthreads();
    int o = tid;
    float acc[16];
    float bb = mlpb[o];
    #pragma unroll
    for (int i = 0; i < 16; ++i) acc[i] = bb;
    for (int k = 0; k < MIN_; ++k) {
        float wv = g_mlpWT[k * HID_ + o];
        #pragma unroll
        for (int i = 0; i < 16; ++i) acc[i] += sIn[i * MIN_ + k] * wv;
    }
    #pragma unroll
    for (int i = 0; i < 16; ++i)
        g_hidF[(size_t)(rbase + i) * HID_ + o] = tanhf(acc[i]);
}

// ---------------- K5: out = hidden @ fc_W^T + fc_b  (single fp16 mma) ----------------
// M-tile 256 (A resident, 256x264 halves). B handled as K-chunks of 128 cols:
// each smem buffer = 128 rows x 136 halves; 2 buffers, pipelined at chunk level.
// Accumulators persist across the 2 chunks of a tile. grid (37,4) = 148 CTAs.
#define NTILES 782
#define FC_SMEM (256 * 264 * 2 + 2 * 128 * 136 * 2)   // 204800
__global__ void __launch_bounds__(512, 1) k_fc(const float* __restrict__ fcb,
                                               float* __restrict__ out) {
    extern __shared__ __half sm5[];
    __half* Ah = sm5;                   // 256 x 264 (full K=256)
    __half* Bb = sm5 + 256 * 264;       // 2 x (128 x 136), one K-chunk each
    int tid = threadIdx.x;
    int m0 = blockIdx.y * 256;

    // load A (hidden fp32 -> fp16), resident for whole kernel
    #pragma unroll
    for (int it = 0; it < 32; ++it) {
        int lin = tid + it * 512;        // 0..16383 float4 units
        int row = lin >> 6;
        int c4  = lin & 63;
        float4 v = *(const float4*)(g_hidF + (size_t)(m0 + row) * HID_ + c4 * 4);
        *(__half2*)(Ah + row * 264 + c4 * 4)     = __floats2half2_rn(v.x, v.y);
        *(__half2*)(Ah + row * 264 + c4 * 4 + 2) = __floats2half2_rn(v.z, v.w);
    }

    int w = tid >> 5, lane = tid & 31;
    int wm = (w >> 2) * 64, wn = (w & 3) * 32;
    int r = lane >> 2, q = (lane & 3) * 2;

    // load one K-chunk (128 halves) of tile nt into buffer buf
    auto loadChunk = [&](int nt, int kc, int buf) {
        int n0 = nt * 128;
        __half* dst = Bb + buf * 128 * 136;
        #pragma unroll
        for (int it = 0; it < 4; ++it) {
            int lin = tid + it * 512;    // 0..2047 uint4 chunks (128 rows x 16)
            int row = lin >> 4;
            int ch  = lin & 15;
            if (n0 + row < V_)
                cp_async16(dst + row * 136 + ch * 8,
                           g_fcHi + (size_t)(n0 + row) * HID_ + kc * 128 + ch * 8);
            else
                *(uint4*)(dst + row * 136 + ch * 8) = make_uint4(0u, 0u, 0u, 0u);
        }
        asm volatile("cp.async.commit_group;");
    };

    int grid = gridDim.x;
    int nt = blockIdx.x;
    loadChunk(nt, 0, 0);
    int buf = 0;

    for (; nt < NTILES; nt += grid) {
        float c[4][4][4];
        #pragma unroll
        for (int mi = 0; mi < 4; ++mi)
            #pragma unroll
            for (int j = 0; j < 4; ++j)
                #pragma unroll
                for (int t = 0; t < 4; ++t) c[mi][j][t] = 0.f;

        #pragma unroll
        for (int kc = 0; kc < 2; ++kc) {
            // prefetch next chunk: (nt,1) if kc==0, else (nt+grid,0)
            int nnt = (kc == 0) ? nt : nt + grid;
            int nkc = kc ^ 1;
            __syncthreads();                       // prior compute on buf^1 done
            if (nnt < NTILES) {
                loadChunk(nnt, nkc, buf ^ 1);
                asm volatile("cp.async.wait_group 1;");
            } else {
                asm volatile("cp.async.wait_group 0;");
            }
            __syncthreads();                       // current buf visible

            const __half* B0 = Bb + buf * 128 * 136;
            #pragma unroll
            for (int ks = 0; ks < 8; ++ks) {
                int k0 = ks * 16;                  // within-chunk K offset (<=112)
                int ka = kc * 128 + k0;            // A K offset
                unsigned a[4][4];
                #pragma unroll
                for (int mi = 0; mi < 4; ++mi) {
                    const __half* p = Ah + (wm + mi * 16) * 264 + ka;
                    a[mi][0] = *(const unsigned*)(p + r * 264 + q);
                    a[mi][1] = *(const unsigned*)(p + (r + 8) * 264 + q);
                    a[mi][2] = *(const unsigned*)(p + r * 264 + 8 + q);
                    a[mi][3] = *(const unsigned*)(p + (r + 8) * 264 + 8 + q);
                }
                #pragma unroll
                for (int j = 0; j < 4; ++j) {
                    const __half* pb = B0 + (wn + j * 8 + r) * 136 + k0;
                    unsigned b0 = *(const unsigned*)(pb + q);
                    unsigned b1 = *(const unsigned*)(pb + 8 + q);
                    #pragma unroll
                    for (int mi = 0; mi < 4; ++mi)
                        mma16816(c[mi][j], a[mi], b0, b1);
                }
            }
            buf ^= 1;
        }

        int n0 = nt * 128;
        #pragma unroll
        for (int mi = 0; mi < 4; ++mi) {
            int row = m0 + wm + mi * 16 + r;
            #pragma unroll
            for (int j = 0; j < 4; ++j) {
                int col = n0 + wn + j * 8 + q;
                if (col < V_) {
                    float2 bv = *(const float2*)(fcb + col);
                    *(float2*)(out + (size_t)row * V_ + col) =
                        make_float2(c[mi][j][0] + bv.x, c[mi][j][1] + bv.y);
                    *(float2*)(out + (size_t)(row + 8) * V_ + col) =
                        make_float2(c[mi][j][2] + bv.x, c[mi][j][3] + bv.y);
                }
            }
        }
    }
}

// ---------------- launch ----------------
extern "C" void kernel_launch(void* const* d_in, const int* in_sizes, int n_in,
                              void* d_out, int out_size) {
    const int*   seq   = (const int*)d_in[0];
    const int*   tlen  = (const int*)d_in[1];
    const float* emb   = (const float*)d_in[2];
    const float* kg    = (const float*)d_in[3];
    const float* Wih   = (const float*)d_in[4];
    const float* Whh   = (const float*)d_in[5];
    const float* bih   = (const float*)d_in[6];
    const float* bhh   = (const float*)d_in[7];
    const float* mlphW = (const float*)d_in[8];
    const float* mlphb = (const float*)d_in[9];
    const float* mlpW  = (const float*)d_in[10];
    const float* mlpb  = (const float*)d_in[11];
    const float* fcW   = (const float*)d_in[12];
    const float* fcb   = (const float*)d_in[13];
    float* out = (float*)d_out;

    cudaFuncSetAttribute(k_gx,  cudaFuncAttributeMaxDynamicSharedMemorySize, GX_SMEM);
    cudaFuncSetAttribute(k_gru, cudaFuncAttributeMaxDynamicSharedMemorySize, GRU_SMEM);
    cudaFuncSetAttribute(k_fc,  cudaFuncAttributeMaxDynamicSharedMemorySize, FC_SMEM);

    k_kgstat<<<200, 256>>>(kg);
    k_kgfin<<<1, 64>>>();
    k_cvt_small<<<192, 256>>>(Wih, Whh, mlpW);
    k_cvt_fc<<<2048, 256>>>(fcW);
    k_gx<<<dim3(400, 3), 512, GX_SMEM>>>(seq, emb, bih);
    k_bkg<<<1024, 64>>>(seq, tlen, kg, mlphW, mlphb);
    k_gru<<<128, 256, GRU_SMEM>>>(tlen, bhh);
    k_mlp<<<64, 256>>>(mlpb);
    k_fc<<<dim3(37, 4), 512, FC_SMEM>>>(fcb, out);
}

// round 8
// speedup vs baseline: 1.8660x; 1.1229x over previous
#include <cuda_runtime.h>
#include <cuda_fp16.h>

#define V_    100000
#define B_    1024
#define L_    50
#define D_    128
#define KG_   50
#define TD_   384      // 3*D
#define HID_  256      // 2*D
#define MIN_  228      // D + 2*KG

// ---------------- static device scratch ----------------
__device__ float  g_part[200 * 128];
__device__ float  g_mean[64];
__device__ float  g_invstd[64];
__device__ __half g_gxH[(size_t)B_ * L_ * TD_];    // 39.3 MB (fp16 gx)
__device__ __half g_WihH[TD_ * D_];
__device__ __half g_WhhH[TD_ * D_];
__device__ __half g_fcH[(size_t)V_ * HID_];        // 51.2 MB
__device__ float  g_mlpWT[MIN_ * HID_];
__device__ float  g_head[B_ * MIN_];
__device__ float  g_hidF[B_ * HID_];

// ---------------- helpers ----------------
__device__ __forceinline__ void mma16816(float c[4], const unsigned a[4],
                                         unsigned b0, unsigned b1) {
    asm volatile(
        "mma.sync.aligned.m16n8k16.row.col.f32.f16.f16.f32 "
        "{%0,%1,%2,%3}, {%4,%5,%6,%7}, {%8,%9}, {%0,%1,%2,%3};"
        : "+f"(c[0]), "+f"(c[1]), "+f"(c[2]), "+f"(c[3])
        : "r"(a[0]), "r"(a[1]), "r"(a[2]), "r"(a[3]), "r"(b0), "r"(b1));
}

__device__ __forceinline__ void ldsm_x4(unsigned r[4], const __half* p) {
    unsigned addr = (unsigned)__cvta_generic_to_shared(p);
    asm volatile("ldmatrix.sync.aligned.m8n8.x4.shared.b16 {%0,%1,%2,%3}, [%4];"
                 : "=r"(r[0]), "=r"(r[1]), "=r"(r[2]), "=r"(r[3]) : "r"(addr));
}

__device__ __forceinline__ void ldsm_x2(unsigned& r0, unsigned& r1, const __half* p) {
    unsigned addr = (unsigned)__cvta_generic_to_shared(p);
    asm volatile("ldmatrix.sync.aligned.m8n8.x2.shared.b16 {%0,%1}, [%2];"
                 : "=r"(r0), "=r"(r1) : "r"(addr));
}

__device__ __forceinline__ void cp_async16(void* smem_dst, const void* gmem_src) {
    unsigned s = (unsigned)__cvta_generic_to_shared(smem_dst);
    asm volatile("cp.async.cg.shared.global [%0], [%1], 16;" :: "r"(s), "l"(gmem_src));
}

__device__ __forceinline__ float sigm_f(float x) {
    return __fdividef(1.f, 1.f + __expf(-x));
}

// ---------------- K_pre: kgstat partials + small cvts + fc cvt (fused) ----------------
__global__ void __launch_bounds__(256) k_pre(const float* __restrict__ kg,
                                             const float* __restrict__ Wih,
                                             const float* __restrict__ Whh,
                                             const float* __restrict__ mlpW,
                                             const float* __restrict__ fcW) {
    __shared__ float ss[4][64], sq[4][64];
    int b = blockIdx.x;
    if (b < 200) {
        int c  = threadIdx.x & 63;
        int rg = threadIdx.x >> 6;
        int r0 = b * 500;
        float s = 0.f, q = 0.f;
        if (c < KG_) {
            for (int r = r0 + rg; r < r0 + 500; r += 4) {
                float v = kg[(size_t)r * KG_ + c];
                s += v; q += v * v;
            }
        }
        ss[rg][c] = s; sq[rg][c] = q;
        __syncthreads();
        if (rg == 0 && c < KG_) {
            float S = ss[0][c] + ss[1][c] + ss[2][c] + ss[3][c];
            float Q = sq[0][c] + sq[1][c] + sq[2][c] + sq[3][c];
            g_part[b * 128 + c]      = S;
            g_part[b * 128 + 64 + c] = Q;
        }
    } else if (b < 392) {
        int i = (b - 200) * 256 + threadIdx.x;
        int stride = 192 * 256;
        for (int j = i; j < TD_ * D_; j += stride) {
            g_WihH[j] = __float2half_rn(Wih[j]);
            g_WhhH[j] = __float2half_rn(Whh[j]);
        }
        for (int j = i; j < HID_ * MIN_; j += stride) {
            int o = j / MIN_, k = j % MIN_;
            g_mlpWT[k * HID_ + o] = mlpW[j];
        }
    } else {
        size_t n = (size_t)V_ * HID_ / 4;
        size_t stride = (size_t)2048 * 256;
        for (size_t j = (size_t)(b - 392) * 256 + threadIdx.x; j < n; j += stride) {
            float4 v = ((const float4*)fcW)[j];
            ((__half2*)g_fcH)[j * 2]     = __floats2half2_rn(v.x, v.y);
            ((__half2*)g_fcH)[j * 2 + 1] = __floats2half2_rn(v.z, v.w);
        }
    }
}

// ---------------- K0b: finalize mean/invstd ----------------
__global__ void k_kgfin() {
    int c = threadIdx.x;
    if (c >= KG_) return;
    float S = 0.f, Q = 0.f;
    for (int i = 0; i < 200; ++i) {
        S += g_part[i * 128 + c];
        Q += g_part[i * 128 + 64 + c];
    }
    float mu  = S / (float)V_;
    float var = Q / (float)V_ - mu * mu;
    g_mean[c]   = mu;
    g_invstd[c] = rsqrtf(var + 1e-5f);
}

// ---------------- K1: GX = gather(item_emb) @ Wih^T + bih  (fp16, fp16 out) ----------------
#define GX_SMEM (2 * 128 * 136 * 2)   // 69632
__global__ void __launch_bounds__(512, 1) k_gx(const int* __restrict__ seq,
                                               const float* __restrict__ emb,
                                               const float* __restrict__ bih) {
    extern __shared__ __half sm1[];
    __half* Ah = sm1;                 // 128 x 136
    __half* Bh = sm1 + 128 * 136;     // 128 x 136
    int tid = threadIdx.x;
    int m0 = blockIdx.x * 128;
    int n0 = blockIdx.y * 128;

    #pragma unroll
    for (int it = 0; it < 8; ++it) {
        int lin = tid + it * 512;        // 0..4095
        int row = lin >> 5;
        int f4  = lin & 31;
        int v = seq[m0 + row];
        float4 x = *(const float4*)(emb + (size_t)v * D_ + f4 * 4);
        *(__half2*)(Ah + row * 136 + f4 * 4)     = __floats2half2_rn(x.x, x.y);
        *(__half2*)(Ah + row * 136 + f4 * 4 + 2) = __floats2half2_rn(x.z, x.w);
    }
    #pragma unroll
    for (int it = 0; it < 4; ++it) {
        int lin = tid + it * 512;        // 0..2047
        int row = lin >> 4;
        int ch  = lin & 15;
        *(uint4*)(Bh + row * 136 + ch * 8) =
            *(const uint4*)(g_WihH + (n0 + row) * D_ + ch * 8);
    }
    __syncthreads();

    int w = tid >> 5, lane = tid & 31;
    int wm = (w >> 2) * 32, wn = (w & 3) * 32;
    int r = lane >> 2, q = (lane & 3) * 2;

    float c[2][4][4];
    #pragma unroll
    for (int i = 0; i < 2; ++i)
        #pragma unroll
        for (int j = 0; j < 4; ++j)
            #pragma unroll
            for (int t = 0; t < 4; ++t) c[i][j][t] = 0.f;

    #pragma unroll
    for (int ks = 0; ks < 8; ++ks) {
        int k0 = ks * 16;
        unsigned a[2][4];
        #pragma unroll
        for (int i = 0; i < 2; ++i) {
            const __half* p = Ah + (wm + i * 16) * 136 + k0;
            a[i][0] = *(const unsigned*)(p + r * 136 + q);
            a[i][1] = *(const unsigned*)(p + (r + 8) * 136 + q);
            a[i][2] = *(const unsigned*)(p + r * 136 + 8 + q);
            a[i][3] = *(const unsigned*)(p + (r + 8) * 136 + 8 + q);
        }
        #pragma unroll
        for (int j = 0; j < 4; ++j) {
            const __half* pb = Bh + (wn + j * 8 + r) * 136 + k0;
            unsigned b0 = *(const unsigned*)(pb + q);
            unsigned b1 = *(const unsigned*)(pb + 8 + q);
            mma16816(c[0][j], a[0], b0, b1);
            mma16816(c[1][j], a[1], b0, b1);
        }
    }
    #pragma unroll
    for (int i = 0; i < 2; ++i) {
        int row = m0 + wm + i * 16 + r;
        #pragma unroll
        for (int j = 0; j < 4; ++j) {
            int col = n0 + wn + j * 8 + q;
            float b0 = __ldg(bih + col), b1 = __ldg(bih + col + 1);
            *(__half2*)(g_gxH + (size_t)row * TD_ + col) =
                __floats2half2_rn(c[i][j][0] + b0, c[i][j][1] + b1);
            *(__half2*)(g_gxH + (size_t)(row + 8) * TD_ + col) =
                __floats2half2_rn(c[i][j][2] + b0, c[i][j][3] + b1);
        }
    }
}

// ---------------- K3: batch_kg + mlph -> g_head[:,128:228] ----------------
__global__ void k_bkg(const int* __restrict__ seq, const int* __restrict__ tlen,
                      const float* __restrict__ kg,
                      const float* __restrict__ mlphW, const float* __restrict__ mlphb) {
    int b = blockIdx.x, c = threadIdx.x;
    __shared__ int   sseq[L_];
    __shared__ float sbkg[KG_];
    if (c < L_) sseq[c] = seq[b * L_ + c];
    __syncthreads();
    if (c < KG_) {
        float acc = 0.f;
        #pragma unroll 10
        for (int t = 0; t < L_; ++t) acc += kg[(size_t)sseq[t] * KG_ + c];
        float val = (acc - (float)L_ * g_mean[c]) * g_invstd[c] / (float)tlen[b];
        sbkg[c] = val;
        g_head[b * MIN_ + D_ + c] = val;
    }
    __syncthreads();
    if (c < KG_) {
        float acc = mlphb[c];
        #pragma unroll 10
        for (int k = 0; k < KG_; ++k) acc += sbkg[k] * mlphW[c * KG_ + k];
        g_head[b * MIN_ + D_ + KG_ + c] = acc;
    }
}

// ---------------- K2: GRU recurrence (8 batch rows per CTA), fp16 gx ----------------
// smem: sWhh 104448 | sH16 4352 | sGx 12288 | sGh 24832 | sHf 8192 | sBhh 1536 | slen 32
#define GRU_SMEM 155680
__global__ void __launch_bounds__(256, 1) k_gru(const int* __restrict__ tlen,
                                                const float* __restrict__ bhh) {
    extern __shared__ char smraw[];
    __half* sWhh = (__half*)smraw;                 // 384 x 136
    __half* sH16 = sWhh + 52224;                   // 16 x 136
    __half* sGx  = sH16 + 2176;                    // 2 x 3072 halves
    float*  sGh  = (float*)(sGx + 6144);           // 16 x 388
    float*  sHf  = sGh + 6208;                     // 16 x 128
    float*  sBhh = sHf + 2048;                     // 384
    int*    slen = (int*)(sBhh + 384);             // 8

    int tid = threadIdx.x;
    int rbase = blockIdx.x * 8;

    #pragma unroll
    for (int j = 0; j < 24; ++j) {
        int lin = tid + j * 256;
        int row = lin >> 4;
        int ch  = lin & 15;
        *(uint4*)(sWhh + row * 136 + ch * 8) = *(const uint4*)(g_WhhH + row * D_ + ch * 8);
    }
    for (int j = tid; j < 2048; j += 256) sHf[j] = 0.f;
    for (int j = tid; j < 384; j += 256) sBhh[j] = bhh[j];
    if (tid < 8)   slen[tid] = tlen[rbase + tid];

    // prefetch gx(t=0): 8 rows x 384 halves = 384 16B-chunks
    #pragma unroll
    for (int j = 0; j < 2; ++j) {
        int e = tid + j * 256;
        if (e < 384) {
            int rr = e / 48, qq = e % 48;
            cp_async16(sGx + rr * 384 + qq * 8,
                       g_gxH + ((size_t)(rbase + rr) * L_) * TD_ + qq * 8);
        }
    }
    asm volatile("cp.async.commit_group;");
    __syncthreads();

    int maxlen = 0;
    #pragma unroll
    for (int i = 0; i < 8; ++i) maxlen = max(maxlen, slen[i]);

    int lane = tid & 31, w = tid >> 5;
    int r = lane >> 2, q2 = (lane & 3) * 2;

    for (int t = 0; t < maxlen; ++t) {
        int buf = t & 1;
        if (t + 1 < maxlen) {
            #pragma unroll
            for (int j = 0; j < 2; ++j) {
                int e = tid + j * 256;
                if (e < 384) {
                    int rr = e / 48, qq = e % 48;
                    cp_async16(sGx + (buf ^ 1) * 3072 + rr * 384 + qq * 8,
                               g_gxH + ((size_t)(rbase + rr) * L_ + (t + 1)) * TD_ + qq * 8);
                }
            }
        }
        asm volatile("cp.async.commit_group;");

        #pragma unroll
        for (int j = 0; j < 4; ++j) {
            int e = tid + j * 256;
            int rr = e >> 6, dd = (e & 63) * 2;
            *(__half2*)(sH16 + rr * 136 + dd) =
                __floats2half2_rn(sHf[rr * 128 + dd], sHf[rr * 128 + dd + 1]);
        }
        asm volatile("cp.async.wait_group 1;");
        __syncthreads();

        {
            float c[6][4];
            #pragma unroll
            for (int j = 0; j < 6; ++j) c[j][0] = c[j][1] = c[j][2] = c[j][3] = 0.f;
            #pragma unroll
            for (int ks = 0; ks < 8; ++ks) {
                int k0 = ks * 16;
                unsigned a[4];
                a[0] = *(const unsigned*)(sH16 + r * 136 + k0 + q2);
                a[1] = *(const unsigned*)(sH16 + (r + 8) * 136 + k0 + q2);
                a[2] = *(const unsigned*)(sH16 + r * 136 + k0 + 8 + q2);
                a[3] = *(const unsigned*)(sH16 + (r + 8) * 136 + k0 + 8 + q2);
                #pragma unroll
                for (int j = 0; j < 6; ++j) {
                    const __half* bb = sWhh + (w * 48 + j * 8 + r) * 136 + k0;
                    unsigned b0 = *(const unsigned*)(bb + q2);
                    unsigned b1 = *(const unsigned*)(bb + 8 + q2);
                    mma16816(c[j], a, b0, b1);
                }
            }
            #pragma unroll
            for (int j = 0; j < 6; ++j) {
                int col = w * 48 + j * 8 + q2;
                *(float2*)(sGh + r * 388 + col)       = make_float2(c[j][0], c[j][1]);
                *(float2*)(sGh + (r + 8) * 388 + col) = make_float2(c[j][2], c[j][3]);
            }
        }
        __syncthreads();

        #pragma unroll
        for (int j = 0; j < 4; ++j) {
            int e = tid + j * 256;
            int rr = e >> 7, dd = e & 127;
            if (t < slen[rr]) {
                const __half* gx = sGx + buf * 3072 + rr * 384;
                float ghr = sGh[rr * 388 + dd]       + sBhh[dd];
                float ghz = sGh[rr * 388 + 128 + dd] + sBhh[128 + dd];
                float ghn = sGh[rr * 388 + 256 + dd] + sBhh[256 + dd];
                float rg = sigm_f(__half2float(gx[dd]) + ghr);
                float z  = sigm_f(__half2float(gx[128 + dd]) + ghz);
                float nn = 2.f * sigm_f(2.f * (__half2float(gx[256 + dd]) + rg * ghn)) - 1.f;
                float h  = sHf[rr * 128 + dd];
                sHf[rr * 128 + dd] = (1.f - z) * nn + z * h;
            }
        }
        __syncthreads();
    }
    asm volatile("cp.async.wait_all;");

    #pragma unroll
    for (int j = 0; j < 4; ++j) {
        int e = tid + j * 256;
        int rr = e >> 7, dd = e & 127;
        g_head[(rbase + rr) * MIN_ + dd] = sHf[rr * 128 + dd];
    }
}

// ---------------- K4: hidden = tanh(g_head @ mlp_W^T + mlp_b) -> fp32 ----------------
__global__ void __launch_bounds__(256) k_mlp(const float* __restrict__ mlpb) {
    __shared__ float sIn[16 * MIN_];
    int tid = threadIdx.x;
    int rbase = blockIdx.x * 16;
    for (int j = tid; j < 16 * MIN_; j += 256) {
        int rr = j / MIN_, kk = j % MIN_;
        sIn[j] = g_head[(rbase + rr) * MIN_ + kk];
    }
    __syncthreads();
    int o = tid;
    float acc[16];
    float bb = mlpb[o];
    #pragma unroll
    for (int i = 0; i < 16; ++i) acc[i] = bb;
    for (int k = 0; k < MIN_; ++k) {
        float wv = g_mlpWT[k * HID_ + o];
        #pragma unroll
        for (int i = 0; i < 16; ++i) acc[i] += sIn[i * MIN_ + k] * wv;
    }
    #pragma unroll
    for (int i = 0; i < 16; ++i)
        g_hidF[(size_t)(rbase + i) * HID_ + o] = tanhf(acc[i]);
}

// ---------------- K5: out = hidden @ fc_W^T + fc_b  (fp16 mma + ldmatrix) ----------------
// M-tile 256 (A resident, 256x264 halves). B as K-chunks of 128: 2 x (128x136)
// buffers, chunk-level cp.async pipeline. grid (37,4) = 148 CTAs.
#define NTILES 782
#define FC_SMEM (256 * 264 * 2 + 2 * 128 * 136 * 2)   // 204800
__global__ void __launch_bounds__(512, 1) k_fc(const float* __restrict__ fcb,
                                               float* __restrict__ out) {
    extern __shared__ __half sm5[];
    __half* Ah = sm5;                   // 256 x 264 (full K=256)
    __half* Bb = sm5 + 256 * 264;       // 2 x (128 x 136)
    int tid = threadIdx.x;
    int m0 = blockIdx.y * 256;

    #pragma unroll
    for (int it = 0; it < 32; ++it) {
        int lin = tid + it * 512;        // 0..16383 float4 units
        int row = lin >> 6;
        int c4  = lin & 63;
        float4 v = *(const float4*)(g_hidF + (size_t)(m0 + row) * HID_ + c4 * 4);
        *(__half2*)(Ah + row * 264 + c4 * 4)     = __floats2half2_rn(v.x, v.y);
        *(__half2*)(Ah + row * 264 + c4 * 4 + 2) = __floats2half2_rn(v.z, v.w);
    }

    int w = tid >> 5, lane = tid & 31;
    int wm = (w >> 2) * 64, wn = (w & 3) * 32;
    int r = lane >> 2, q = (lane & 3) * 2;

    // per-lane ldmatrix offsets (in halves)
    int aoff = (lane & 15) * 264 + (lane >> 4) * 8;
    int boff = (lane & 7) * 136 + ((lane >> 3) & 1) * 8;

    auto loadChunk = [&](int nt, int kc, int buf) {
        int n0 = nt * 128;
        __half* dst = Bb + buf * 128 * 136;
        #pragma unroll
        for (int it = 0; it < 4; ++it) {
            int lin = tid + it * 512;    // 0..2047 (128 rows x 16 chunks)
            int row = lin >> 4;
            int ch  = lin & 15;
            if (n0 + row < V_)
                cp_async16(dst + row * 136 + ch * 8,
                           g_fcH + (size_t)(n0 + row) * HID_ + kc * 128 + ch * 8);
            else
                *(uint4*)(dst + row * 136 + ch * 8) = make_uint4(0u, 0u, 0u, 0u);
        }
        asm volatile("cp.async.commit_group;");
    };

    int grid = gridDim.x;
    int nt = blockIdx.x;
    loadChunk(nt, 0, 0);
    int buf = 0;

    for (; nt < NTILES; nt += grid) {
        float c[4][4][4];
        #pragma unroll
        for (int mi = 0; mi < 4; ++mi)
            #pragma unroll
            for (int j = 0; j < 4; ++j)
                #pragma unroll
                for (int t = 0; t < 4; ++t) c[mi][j][t] = 0.f;

        #pragma unroll
        for (int kc = 0; kc < 2; ++kc) {
            int nnt = (kc == 0) ? nt : nt + grid;
            int nkc = kc ^ 1;
            __syncthreads();
            if (nnt < NTILES) {
                loadChunk(nnt, nkc, buf ^ 1);
                asm volatile("cp.async.wait_group 1;");
            } else {
                asm volatile("cp.async.wait_group 0;");
            }
            __syncthreads();

            const __half* B0 = Bb + buf * 128 * 136;
            #pragma unroll
            for (int ks = 0; ks < 8; ++ks) {
                int k0 = ks * 16;                  // within-chunk (<=112)
                int ka = kc * 128 + k0;            // A offset
                unsigned a[4][4];
                #pragma unroll
                for (int mi = 0; mi < 4; ++mi)
                    ldsm_x4(a[mi], Ah + (wm + mi * 16) * 264 + ka + aoff);
                #pragma unroll
                for (int j = 0; j < 4; ++j) {
                    unsigned b0, b1;
                    ldsm_x2(b0, b1, B0 + (wn + j * 8) * 136 + k0 + boff);
                    #pragma unroll
                    for (int mi = 0; mi < 4; ++mi)
                        mma16816(c[mi][j], a[mi], b0, b1);
                }
            }
            buf ^= 1;
        }

        int n0 = nt * 128;
        #pragma unroll
        for (int mi = 0; mi < 4; ++mi) {
            int row = m0 + wm + mi * 16 + r;
            #pragma unroll
            for (int j = 0; j < 4; ++j) {
                int col = n0 + wn + j * 8 + q;
                if (col < V_) {
                    float2 bv = *(const float2*)(fcb + col);
                    *(float2*)(out + (size_t)row * V_ + col) =
                        make_float2(c[mi][j][0] + bv.x, c[mi][j][1] + bv.y);
                    *(float2*)(out + (size_t)(row + 8) * V_ + col) =
                        make_float2(c[mi][j][2] + bv.x, c[mi][j][3] + bv.y);
                }
            }
        }
    }
}

// ---------------- launch ----------------
extern "C" void kernel_launch(void* const* d_in, const int* in_sizes, int n_in,
                              void* d_out, int out_size) {
    const int*   seq   = (const int*)d_in[0];
    const int*   tlen  = (const int*)d_in[1];
    const float* emb   = (const float*)d_in[2];
    const float* kg    = (const float*)d_in[3];
    const float* Wih   = (const float*)d_in[4];
    const float* Whh   = (const float*)d_in[5];
    const float* bih   = (const float*)d_in[6];
    const float* bhh   = (const float*)d_in[7];
    const float* mlphW = (const float*)d_in[8];
    const float* mlphb = (const float*)d_in[9];
    const float* mlpW  = (const float*)d_in[10];
    const float* mlpb  = (const float*)d_in[11];
    const float* fcW   = (const float*)d_in[12];
    const float* fcb   = (const float*)d_in[13];
    float* out = (float*)d_out;

    cudaFuncSetAttribute(k_gx,  cudaFuncAttributeMaxDynamicSharedMemorySize, GX_SMEM);
    cudaFuncSetAttribute(k_gru, cudaFuncAttributeMaxDynamicSharedMemorySize, GRU_SMEM);
    cudaFuncSetAttribute(k_fc,  cudaFuncAttributeMaxDynamicSharedMemorySize, FC_SMEM);

    k_pre<<<2440, 256>>>(kg, Wih, Whh, mlpW, fcW);
    k_kgfin<<<1, 64>>>();
    k_gx<<<dim3(400, 3), 512, GX_SMEM>>>(seq, emb, bih);
    k_gru<<<128, 256, GRU_SMEM>>>(tlen, bhh);
    k_bkg<<<1024, 64>>>(seq, tlen, kg, mlphW, mlphb);
    k_mlp<<<64, 256>>>(mlpb);
    k_fc<<<dim3(37, 4), 512, FC_SMEM>>>(fcb, out);
}